// round 16
// baseline (speedup 1.0000x reference)
#include <cuda_runtime.h>
#include <cuda_fp16.h>
#include <cstdint>
#include <cstddef>

#define NN 4096
#define DM 256
#define NH 8
#define DH 32

// ---------------- scratch (device globals; no allocation) ----------------
__device__ __half g_P_hi[(size_t)NH * NN * NN];   // relu(QK^T) hi split; REUSED as fp16 attn after softmax
__device__ __half g_P_lo[(size_t)NH * NN * NN];   // lo split
__device__ __half g_RT_hi[(size_t)NN * NN];       // rescale(dist)^T hi, [p][m]
__device__ __half g_RT_lo[(size_t)NN * NN];       // lo split
__device__ float  g_S[(size_t)NH * NN * NN];      // scores
__device__ __half g_Qh[(size_t)NN * DM];          // Q projection fp16 hi/lo
__device__ __half g_Ql[(size_t)NN * DM];
__device__ __half g_Kh[(size_t)NN * DM];
__device__ __half g_Kl[(size_t)NN * DM];
__device__ __half g_VT[(size_t)DM * NN];          // V^T fp16: g_VT[j][n] = V[n][j]

// ---------------- helpers ----------------
__device__ __forceinline__ uint32_t smem_u32(const void* p) {
    uint32_t a;
    asm("{ .reg .u64 t; cvta.to.shared.u64 t, %1; cvt.u32.u64 %0, t; }" : "=r"(a) : "l"(p));
    return a;
}

__device__ __forceinline__ void ldsm_x4(uint32_t* r, uint32_t addr) {
    asm volatile("ldmatrix.sync.aligned.m8n8.x4.shared.b16 {%0,%1,%2,%3}, [%4];"
                 : "=r"(r[0]), "=r"(r[1]), "=r"(r[2]), "=r"(r[3]) : "r"(addr));
}

__device__ __forceinline__ void mma16816(float* c, const uint32_t* a, const uint32_t* b) {
    asm volatile(
        "mma.sync.aligned.m16n8k16.row.col.f32.f16.f16.f32 "
        "{%0,%1,%2,%3}, {%4,%5,%6,%7}, {%8,%9}, {%0,%1,%2,%3};"
        : "+f"(c[0]), "+f"(c[1]), "+f"(c[2]), "+f"(c[3])
        : "r"(a[0]), "r"(a[1]), "r"(a[2]), "r"(a[3]), "r"(b[0]), "r"(b[1]));
}

__device__ __forceinline__ void cp16(uint32_t smem, const void* gmem) {
    asm volatile("cp.async.cg.shared.global [%0], [%1], 16;" :: "r"(smem), "l"(gmem));
}

// ---------------- kernel 1: R^T = rescale(dist)^T, fp16 split ----------------
__global__ void __launch_bounds__(1024) k_rescale(const float* __restrict__ dist) {
    __shared__ float t[32][33];
    const int m0 = blockIdx.y * 32, p0 = blockIdx.x * 32;
    const int tx = threadIdx.x, ty = threadIdx.y;
    float d = dist[(size_t)(m0 + ty) * NN + p0 + tx];
    t[ty][tx] = 3.718281828459045f / (1.0f + __expf(1.0f - d));
    __syncthreads();
    float r = t[tx][ty];  // = R[m0+tx][p0+ty]
    __half hi = __float2half(r);
    float lo = r - __half2float(hi);
    size_t o = (size_t)(p0 + ty) * NN + m0 + tx;
    g_RT_hi[o] = hi;
    g_RT_lo[o] = __float2half(lo);
}

// ---------------- kernel 2a: Q/K projections, tiled 64x64, 4x4 microtile ----------------
__global__ void __launch_bounds__(256) k_projqk(const float* __restrict__ Qin,
                                                const float* __restrict__ Kin,
                                                const float* __restrict__ WQ,
                                                const float* __restrict__ WK) {
    const float* __restrict__ X = blockIdx.z ? Kin : Qin;
    const float* __restrict__ W = blockIdx.z ? WK : WQ;
    __half* Oh = blockIdx.z ? g_Kh : g_Qh;
    __half* Ol = blockIdx.z ? g_Kl : g_Ql;

    __shared__ float Xs[32][68];
    __shared__ float Ws[32][68];
    const int j0g = blockIdx.x * 64, n0g = blockIdx.y * 64;
    const int tid = threadIdx.x;
    const int jt = (tid & 15) * 4;
    const int nt = (tid >> 4) * 4;
    const int lr = tid >> 2;
    const int lc = (tid & 3) * 8;

    float acc[4][4];
#pragma unroll
    for (int a = 0; a < 4; a++)
#pragma unroll
        for (int b = 0; b < 4; b++) acc[a][b] = 0.f;

    for (int k0 = 0; k0 < DM; k0 += 32) {
        __syncthreads();
        float4 a0 = *(const float4*)&X[(size_t)(n0g + lr) * DM + k0 + lc];
        float4 a1 = *(const float4*)&X[(size_t)(n0g + lr) * DM + k0 + lc + 4];
        Xs[lc + 0][lr] = a0.x; Xs[lc + 1][lr] = a0.y; Xs[lc + 2][lr] = a0.z; Xs[lc + 3][lr] = a0.w;
        Xs[lc + 4][lr] = a1.x; Xs[lc + 5][lr] = a1.y; Xs[lc + 6][lr] = a1.z; Xs[lc + 7][lr] = a1.w;
        float4 b0 = *(const float4*)&W[(size_t)(j0g + lr) * DM + k0 + lc];
        float4 b1 = *(const float4*)&W[(size_t)(j0g + lr) * DM + k0 + lc + 4];
        Ws[lc + 0][lr] = b0.x; Ws[lc + 1][lr] = b0.y; Ws[lc + 2][lr] = b0.z; Ws[lc + 3][lr] = b0.w;
        Ws[lc + 4][lr] = b1.x; Ws[lc + 5][lr] = b1.y; Ws[lc + 6][lr] = b1.z; Ws[lc + 7][lr] = b1.w;
        __syncthreads();
#pragma unroll
        for (int kk = 0; kk < 32; kk++) {
            float4 xv = *(const float4*)&Xs[kk][nt];
            float4 wv = *(const float4*)&Ws[kk][jt];
            const float xr[4] = {xv.x, xv.y, xv.z, xv.w};
            const float wr[4] = {wv.x, wv.y, wv.z, wv.w};
#pragma unroll
            for (int a = 0; a < 4; a++)
#pragma unroll
                for (int b = 0; b < 4; b++) acc[a][b] += xr[a] * wr[b];
        }
    }

#pragma unroll
    for (int a = 0; a < 4; a++) {
        const int n = n0g + nt + a;
        __half h[4], l[4];
#pragma unroll
        for (int b = 0; b < 4; b++) {
            h[b] = __float2half(acc[a][b]);
            l[b] = __float2half(acc[a][b] - __half2float(h[b]));
        }
        const size_t o = (size_t)n * DM + j0g + jt;
        *(__half2*)&Oh[o] = __halves2half2(h[0], h[1]);
        *(__half2*)&Oh[o + 2] = __halves2half2(h[2], h[3]);
        *(__half2*)&Ol[o] = __halves2half2(l[0], l[1]);
        *(__half2*)&Ol[o + 2] = __halves2half2(l[2], l[3]);
    }
}

// ---------------- kernel 2b: V projection (transposed fp16 out) ----------------
__global__ void __launch_bounds__(1024) k_projv(const float* __restrict__ X,
                                                const float* __restrict__ W) {
    __shared__ float Xs[32][33], Ws[32][33];
    const int n0 = blockIdx.y * 32, j0 = blockIdx.x * 32;
    const int tx = threadIdx.x, ty = threadIdx.y;
    float acc = 0.f;
    for (int k0 = 0; k0 < DM; k0 += 32) {
        Xs[ty][tx] = X[(size_t)(n0 + ty) * DM + k0 + tx];
        Ws[ty][tx] = W[(size_t)(j0 + ty) * DM + k0 + tx];
        __syncthreads();
#pragma unroll
        for (int kk = 0; kk < 32; kk++) acc += Xs[ty][kk] * Ws[tx][kk];
        __syncthreads();
    }
    __syncthreads();
    Xs[ty][tx] = acc;
    __syncthreads();
    float v = Xs[tx][ty];
    g_VT[(size_t)(j0 + ty) * NN + n0 + tx] = __float2half(v);
}

// ---------------- kernel 3: P = relu(Q K^T) via HMMA, split precision ----------------
// Epilogue staged through smem for coalesced 256B row-segment stores.
#define QK_ROWB 80
#define QK_ARR (128 * QK_ROWB)   // 10240
#define QK_STG_STRIDE 136        // halves per staged row (272B; bank base 4r mod 32)

__global__ void __launch_bounds__(256, 2) k_qk_mma() {
    __shared__ char qsm[4 * QK_ARR];   // operands; reused as 128x136 half staging (34816B)
    const uint32_t sb = smem_u32(qsm);
    const int tid = threadIdx.x;
    const int wid = tid >> 5, lane = tid & 31;
    const int h = blockIdx.z;
    const int m0 = blockIdx.x * 128;   // key tile
    const int n0 = blockIdx.y * 128;   // query tile

    {
        const int r0 = tid >> 2, c = tid & 3;
#pragma unroll
        for (int j = 0; j < 2; j++) {
            const int r = r0 + j * 64;
            const uint32_t so = (uint32_t)(r * QK_ROWB + c * 16);
            const size_t qo = (size_t)(n0 + r) * DM + h * DH + c * 8;
            const size_t ko = (size_t)(m0 + r) * DM + h * DH + c * 8;
            cp16(sb + 0 * QK_ARR + so, g_Qh + qo);
            cp16(sb + 1 * QK_ARR + so, g_Ql + qo);
            cp16(sb + 2 * QK_ARR + so, g_Kh + ko);
            cp16(sb + 3 * QK_ARR + so, g_Kl + ko);
        }
    }
    asm volatile("cp.async.commit_group;" ::: "memory");
    asm volatile("cp.async.wait_group 0;" ::: "memory");
    __syncthreads();

    const int wm = wid & 1, wn = wid >> 1;
    float acc[4][4][4];
#pragma unroll
    for (int mi = 0; mi < 4; mi++)
#pragma unroll
        for (int ni = 0; ni < 4; ni++)
#pragma unroll
            for (int q = 0; q < 4; q++) acc[mi][ni][q] = 0.f;

    const int sel = lane >> 3, l7 = lane & 7;
    const int a_row = wm * 64 + (sel & 1) * 8 + l7;
    const int a_colb = (sel >> 1) * 16;
    const int b_row_base = wn * 32 + (sel >> 1) * 8 + l7;
    const int b_colb = (sel & 1) * 16;

#pragma unroll
    for (int ks = 0; ks < 2; ks++) {
        const int kb = ks * 32;
        uint32_t ahi[4][4], alo[4][4];
#pragma unroll
        for (int mi = 0; mi < 4; mi++) {
            const uint32_t ao = (uint32_t)((a_row + mi * 16) * QK_ROWB + kb + a_colb);
            ldsm_x4(ahi[mi], sb + 0 * QK_ARR + ao);
            ldsm_x4(alo[mi], sb + 1 * QK_ARR + ao);
        }
        uint32_t bhi[4][2], blo[4][2];
#pragma unroll
        for (int nb = 0; nb < 2; nb++) {
            const uint32_t bo = (uint32_t)((b_row_base + nb * 16) * QK_ROWB + kb + b_colb);
            uint32_t t[4];
            ldsm_x4(t, sb + 2 * QK_ARR + bo);
            bhi[2 * nb][0] = t[0]; bhi[2 * nb][1] = t[1];
            bhi[2 * nb + 1][0] = t[2]; bhi[2 * nb + 1][1] = t[3];
            ldsm_x4(t, sb + 3 * QK_ARR + bo);
            blo[2 * nb][0] = t[0]; blo[2 * nb][1] = t[1];
            blo[2 * nb + 1][0] = t[2]; blo[2 * nb + 1][1] = t[3];
        }
#pragma unroll
        for (int mi = 0; mi < 4; mi++)
#pragma unroll
            for (int ni = 0; ni < 4; ni++) mma16816(acc[mi][ni], ahi[mi], bhi[ni]);
#pragma unroll
        for (int mi = 0; mi < 4; mi++)
#pragma unroll
            for (int ni = 0; ni < 4; ni++) mma16816(acc[mi][ni], ahi[mi], blo[ni]);
#pragma unroll
        for (int mi = 0; mi < 4; mi++)
#pragma unroll
            for (int ni = 0; ni < 4; ni++) mma16816(acc[mi][ni], alo[mi], bhi[ni]);
    }

    // staged epilogue: two planes (hi, lo)
    __half* stg = (__half*)qsm;
    const int er = lane >> 2, ec = (lane & 3) * 2;
#pragma unroll
    for (int plane = 0; plane < 2; plane++) {
        __syncthreads();
#pragma unroll
        for (int mi = 0; mi < 4; mi++) {
#pragma unroll
            for (int ni = 0; ni < 4; ni++) {
                const int nl = wm * 64 + mi * 16 + er;       // n-local (row)
                const int ml = wn * 32 + ni * 8 + ec;        // m-local (col)
#pragma unroll
                for (int half = 0; half < 2; half++) {
                    float p0 = fmaxf(acc[mi][ni][2 * half + 0], 0.f);
                    float p1 = fmaxf(acc[mi][ni][2 * half + 1], 0.f);
                    __half v0, v1;
                    if (plane == 0) { v0 = __float2half(p0); v1 = __float2half(p1); }
                    else {
                        __half h0 = __float2half(p0), h1 = __float2half(p1);
                        v0 = __float2half(p0 - __half2float(h0));
                        v1 = __float2half(p1 - __half2float(h1));
                    }
                    *(__half2*)&stg[(nl + half * 8) * QK_STG_STRIDE + ml] = __halves2half2(v0, v1);
                }
            }
        }
        __syncthreads();
        __half* dst = plane == 0 ? g_P_hi : g_P_lo;
#pragma unroll
        for (int i = 0; i < 8; i++) {
            const int idx = i * 256 + tid;
            const int r = idx >> 4, c = idx & 15;      // 16 x 16B chunks per 128-half row
            uint4 v = *(uint4*)&stg[r * QK_STG_STRIDE + c * 8];
            *(uint4*)(dst + ((size_t)h * NN + n0 + r) * NN + m0 + c * 8) = v;
        }
    }
}

// ---------------- kernel 4: big GEMM (HMMA, split precision) ----------------
// CTA tile 256(M) x 128(N), K-chunk 64, 2-stage cp.async, 512 threads, 1 CTA/SM.
// Epilogue staged through smem (two 128-row passes) for 512B coalesced stores.
#define ROWB 144
#define A_ARR (256 * ROWB)               // 36864
#define B_ARR (128 * ROWB)               // 18432
#define STAGE_SZ (2 * A_ARR + 2 * B_ARR) // 110592
#define GEMM_SMEM (2 * STAGE_SZ)         // 221184
#define KITERS (NN / 64)                 // 64
#define G_STG_STRIDE 136                 // floats per staged row (544B)

__global__ void __launch_bounds__(512, 1) k_gemm() {
    extern __shared__ char smem[];
    const uint32_t sb = smem_u32(smem);
    const int tid = threadIdx.x;
    const int wid = tid >> 5, lane = tid & 31;
    const int h = blockIdx.y;

    // swizzle: groups of 8(m) x 16(n) CTAs -> 64MB working set, fits L2
    const int bid = blockIdx.x;          // 0..511
    const int g = bid >> 7;              // 0..3
    const int gx = g & 1, gy = g >> 1;
    const int ny = gy * 8 + (bid & 7);          // m-tile (256 rows)
    const int nx = gx * 16 + ((bid >> 3) & 15); // n-tile (128 cols)
    const int m0 = ny * 256, n0 = nx * 128;

    const __half* __restrict__ Ahi = g_P_hi + ((size_t)h * NN + m0) * NN;
    const __half* __restrict__ Alo = g_P_lo + ((size_t)h * NN + m0) * NN;
    const __half* __restrict__ Bhi = g_RT_hi + (size_t)n0 * NN;
    const __half* __restrict__ Blo = g_RT_lo + (size_t)n0 * NN;

    const int rl = tid >> 3, cl = tid & 7;   // loader: 64 rows x 8 chunks per pass

    auto issue_stage = [&](int it) {
        if (it < KITERS) {
            const uint32_t s0 = sb + (it & 1) * STAGE_SZ;
            const int kc = it * 64;
#pragma unroll
            for (int i = 0; i < 4; i++) {        // A: 256 rows
                const int r = rl + i * 64;
                const uint32_t so = (uint32_t)(r * ROWB + cl * 16);
                const size_t go = (size_t)r * NN + kc + cl * 8;
                cp16(s0 + 0 * A_ARR + so, Ahi + go);
                cp16(s0 + 1 * A_ARR + so, Alo + go);
            }
#pragma unroll
            for (int i = 0; i < 2; i++) {        // B: 128 rows
                const int r = rl + i * 64;
                const uint32_t so = (uint32_t)(r * ROWB + cl * 16);
                const size_t go = (size_t)r * NN + kc + cl * 8;
                cp16(s0 + 2 * A_ARR + 0 * B_ARR + so, Bhi + go);
                cp16(s0 + 2 * A_ARR + 1 * B_ARR + so, Blo + go);
            }
        }
        asm volatile("cp.async.commit_group;" ::: "memory");
    };

    // warp layout: 4 (M) x 4 (N); warp tile 64 (M) x 32 (N)
    const int wm = wid & 3, wn = wid >> 2;
    float acc[4][4][4];
#pragma unroll
    for (int mi = 0; mi < 4; mi++)
#pragma unroll
        for (int ni = 0; ni < 4; ni++)
#pragma unroll
            for (int q = 0; q < 4; q++) acc[mi][ni][q] = 0.f;

    const int sel = lane >> 3, l7 = lane & 7;
    const int a_row = wm * 64 + (sel & 1) * 8 + l7;
    const int a_colb = (sel >> 1) * 16;
    const int b_row_base = wn * 32 + (sel >> 1) * 8 + l7;
    const int b_colb = (sel & 1) * 16;

    issue_stage(0);

    for (int it = 0; it < KITERS; it++) {
        asm volatile("cp.async.wait_group 0;" ::: "memory");
        __syncthreads();            // all warps past previous compute; this stage visible
        issue_stage(it + 1);        // fill other buffer while computing this one

        const uint32_t s0 = sb + (it & 1) * STAGE_SZ;
        const uint32_t pAhi = s0, pAlo = s0 + A_ARR;
        const uint32_t pBhi = s0 + 2 * A_ARR, pBlo = pBhi + B_ARR;

#pragma unroll
        for (int ks = 0; ks < 4; ks++) {   // four k16 steps within the 64-chunk
            const int kb = ks * 32;
            uint32_t ahi[4][4], alo[4][4];
#pragma unroll
            for (int mi = 0; mi < 4; mi++) {
                const uint32_t ao = (uint32_t)((a_row + mi * 16) * ROWB + kb + a_colb);
                ldsm_x4(ahi[mi], pAhi + ao);
                ldsm_x4(alo[mi], pAlo + ao);
            }
            uint32_t bhi[4][2], blo[4][2];
#pragma unroll
            for (int nb = 0; nb < 2; nb++) {
                const uint32_t bo = (uint32_t)((b_row_base + nb * 16) * ROWB + kb + b_colb);
                uint32_t t[4];
                ldsm_x4(t, pBhi + bo);
                bhi[2 * nb][0] = t[0]; bhi[2 * nb][1] = t[1];
                bhi[2 * nb + 1][0] = t[2]; bhi[2 * nb + 1][1] = t[3];
                ldsm_x4(t, pBlo + bo);
                blo[2 * nb][0] = t[0]; blo[2 * nb][1] = t[1];
                blo[2 * nb + 1][0] = t[2]; blo[2 * nb + 1][1] = t[3];
            }
#pragma unroll
            for (int mi = 0; mi < 4; mi++)
#pragma unroll
                for (int ni = 0; ni < 4; ni++) mma16816(acc[mi][ni], ahi[mi], bhi[ni]);
#pragma unroll
            for (int mi = 0; mi < 4; mi++)
#pragma unroll
                for (int ni = 0; ni < 4; ni++) mma16816(acc[mi][ni], ahi[mi], blo[ni]);
#pragma unroll
            for (int mi = 0; mi < 4; mi++)
#pragma unroll
                for (int ni = 0; ni < 4; ni++) mma16816(acc[mi][ni], alo[mi], bhi[ni]);
        }
    }

    // staged epilogue: two passes over M (128 rows each), 512B coalesced stores
    const float inv_s = 0.17677669529663687f;  // 1/sqrt(32)
    float* stg = (float*)smem;                 // 128 x 136 floats = 69632B, fits stage buffer
    const int er = lane >> 2, ec = (lane & 3) * 2;
#pragma unroll
    for (int pass = 0; pass < 2; pass++) {
        __syncthreads();
        if ((wm >> 1) == pass) {
#pragma unroll
            for (int mi = 0; mi < 4; mi++) {
#pragma unroll
                for (int ni = 0; ni < 4; ni++) {
                    const int ml = (wm & 1) * 64 + mi * 16 + er;
                    const int nl = wn * 32 + ni * 8 + ec;
                    *(float2*)&stg[ml * G_STG_STRIDE + nl] =
                        make_float2(acc[mi][ni][0] * inv_s, acc[mi][ni][1] * inv_s);
                    *(float2*)&stg[(ml + 8) * G_STG_STRIDE + nl] =
                        make_float2(acc[mi][ni][2] * inv_s, acc[mi][ni][3] * inv_s);
                }
            }
        }
        __syncthreads();
#pragma unroll
        for (int i = 0; i < 8; i++) {
            const int idx = i * 512 + tid;
            const int r = idx >> 5, c = (idx & 31) * 4;   // warp per row, float4 per lane
            float4 v = *(float4*)&stg[r * G_STG_STRIDE + c];
            *(float4*)(g_S + ((size_t)h * NN + m0 + pass * 128 + r) * NN + n0 + c) = v;
        }
    }
}

// ---------------- kernel 5: softmax, warp-granular exp skip; fp16 attn out ----------------
__global__ void __launch_bounds__(256) k_softmax() {
    const size_t row = blockIdx.x;
    const float* p = g_S + row * (size_t)NN;
    __half* pa = g_P_hi + row * (size_t)NN;
    const int tid = threadIdx.x;
    float x[16];
    float mx = -1e30f;
#pragma unroll
    for (int i = 0; i < 16; i++) { x[i] = p[tid + (i << 8)]; mx = fmaxf(mx, x[i]); }
    __shared__ float red[8];
#pragma unroll
    for (int o = 16; o; o >>= 1) mx = fmaxf(mx, __shfl_xor_sync(0xffffffffu, mx, o));
    if ((tid & 31) == 0) red[tid >> 5] = mx;
    __syncthreads();
    mx = red[0];
#pragma unroll
    for (int i = 1; i < 8; i++) mx = fmaxf(mx, red[i]);
    const float thr = mx - 20.0f;
    float s = 0.f;
#pragma unroll
    for (int i = 0; i < 16; i++) {
        if (__any_sync(0xffffffffu, x[i] >= thr)) {
            x[i] = (x[i] >= thr) ? __expf(x[i] - mx) : 0.f;
            s += x[i];
        } else {
            x[i] = 0.f;
        }
    }
#pragma unroll
    for (int o = 16; o; o >>= 1) s += __shfl_xor_sync(0xffffffffu, s, o);
    __syncthreads();
    if ((tid & 31) == 0) red[tid >> 5] = s;
    __syncthreads();
    s = ((red[0] + red[1]) + (red[2] + red[3])) + ((red[4] + red[5]) + (red[6] + red[7]));
    const float inv = 1.0f / s;
#pragma unroll
    for (int i = 0; i < 16; i++) pa[tid + (i << 8)] = __float2half(x[i] * inv);
}

// ---------------- kernel 6: out = attn @ V via HMMA ----------------
#define AV_ROWB 272
#define AV_A (64 * AV_ROWB)
#define AV_B (32 * AV_ROWB)
#define AV_STAGE (AV_A + AV_B)
#define AV_SMEM (2 * AV_STAGE)
#define AV_KITERS (NN / 128)

__global__ void __launch_bounds__(256) k_av(float* __restrict__ out) {
    extern __shared__ char avsm[];
    const uint32_t sb = smem_u32(avsm);
    const int tid = threadIdx.x;
    const int wid = tid >> 5, lane = tid & 31;
    const int h = blockIdx.y, n0 = blockIdx.x * 64;

    const __half* __restrict__ A = g_P_hi + ((size_t)h * NN + n0) * NN;   // attn rows
    const __half* __restrict__ B = g_VT + (size_t)(h * DH) * NN;          // V^T rows (d)

    auto issue_stage = [&](int it) {
        if (it < AV_KITERS) {
            const uint32_t s0 = sb + (it & 1) * AV_STAGE;
            const int kc = it * 128;
#pragma unroll
            for (int i = 0; i < 4; i++) {
                const int idx = i * 256 + tid;
                const int r = idx >> 4, c = idx & 15;
                cp16(s0 + (uint32_t)(r * AV_ROWB + c * 16), A + (size_t)r * NN + kc + c * 8);
            }
#pragma unroll
            for (int i = 0; i < 2; i++) {
                const int idx = i * 256 + tid;
                const int r = idx >> 4, c = idx & 15;
                cp16(s0 + AV_A + (uint32_t)(r * AV_ROWB + c * 16), B + (size_t)r * NN + kc + c * 8);
            }
        }
        asm volatile("cp.async.commit_group;" ::: "memory");
    };

    const int wm = wid & 3, wn = wid >> 2;
    float acc[2][4];
#pragma unroll
    for (int ni = 0; ni < 2; ni++)
#pragma unroll
        for (int q = 0; q < 4; q++) acc[ni][q] = 0.f;

    const int sel = lane >> 3, l7 = lane & 7;
    const int a_row = wm * 16 + (sel & 1) * 8 + l7;
    const int a_colb = (sel >> 1) * 16;
    const int b_row = wn * 16 + (sel >> 1) * 8 + l7;
    const int b_colb = (sel & 1) * 16;

    issue_stage(0);

    for (int it = 0; it < AV_KITERS; it++) {
        asm volatile("cp.async.wait_group 0;" ::: "memory");
        __syncthreads();
        issue_stage(it + 1);

        const uint32_t s0 = sb + (it & 1) * AV_STAGE;
#pragma unroll
        for (int ks = 0; ks < 8; ks++) {
            const int kb = ks * 32;
            uint32_t a[4], b[4];
            ldsm_x4(a, s0 + (uint32_t)(a_row * AV_ROWB + kb + a_colb));
            ldsm_x4(b, s0 + AV_A + (uint32_t)(b_row * AV_ROWB + kb + b_colb));
            mma16816(acc[0], a, b + 0);
            mma16816(acc[1], a, b + 2);
        }
    }

    const int er = lane >> 2, ec = (lane & 3) * 2;
    const int n = n0 + wm * 16 + er;
#pragma unroll
    for (int ni = 0; ni < 2; ni++) {
        const int d = wn * 16 + ni * 8 + ec;
        *(float2*)(out + (size_t)n * DM + h * DH + d) = make_float2(acc[ni][0], acc[ni][1]);
        *(float2*)(out + (size_t)(n + 8) * DM + h * DH + d) = make_float2(acc[ni][2], acc[ni][3]);
    }
}

// ---------------- launch ----------------
extern "C" void kernel_launch(void* const* d_in, const int* in_sizes, int n_in,
                              void* d_out, int out_size) {
    (void)in_sizes; (void)n_in; (void)out_size;
    const float* Qin  = (const float*)d_in[0];
    const float* Kin  = (const float*)d_in[1];
    const float* Vin  = (const float*)d_in[2];
    // d_in[3] = adj_matrix: dead code in the reference
    const float* dist = (const float*)d_in[4];
    const float* WQ   = (const float*)d_in[5];
    const float* WK   = (const float*)d_in[6];
    const float* WV   = (const float*)d_in[7];
    float* out = (float*)d_out;

    k_rescale<<<dim3(128, 128), dim3(32, 32)>>>(dist);
    k_projqk<<<dim3(4, 64, 2), 256>>>(Qin, Kin, WQ, WK);
    k_projv<<<dim3(8, 128), dim3(32, 32)>>>(Vin, WV);
    k_qk_mma<<<dim3(32, 32, 8), 256>>>();

    cudaFuncSetAttribute(k_gemm, cudaFuncAttributeMaxDynamicSharedMemorySize, GEMM_SMEM);
    k_gemm<<<dim3(512, 8), 512, GEMM_SMEM>>>();

    k_softmax<<<dim3(NH * NN), 256>>>();

    cudaFuncSetAttribute(k_av, cudaFuncAttributeMaxDynamicSharedMemorySize, AV_SMEM);
    k_av<<<dim3(64, 8), 256, AV_SMEM>>>(out);
}

// round 17
// speedup vs baseline: 1.0159x; 1.0159x over previous
#include <cuda_runtime.h>
#include <cuda_fp16.h>
#include <cstdint>
#include <cstddef>

#define NN 4096
#define DM 256
#define NH 8
#define DH 32

// ---------------- scratch (device globals; no allocation) ----------------
__device__ __half g_P_hi[(size_t)NH * NN * NN];   // relu(QK^T) hi split; REUSED as fp16 attn after softmax
__device__ __half g_P_lo[(size_t)NH * NN * NN];   // lo split
__device__ __half g_RT_hi[(size_t)NN * NN];       // rescale(dist)^T hi, [p][m]
__device__ __half g_RT_lo[(size_t)NN * NN];       // lo split
__device__ float  g_S[(size_t)NH * NN * NN];      // scores
__device__ __half g_Qh[(size_t)NN * DM];          // Q projection fp16 hi/lo
__device__ __half g_Ql[(size_t)NN * DM];
__device__ __half g_Kh[(size_t)NN * DM];
__device__ __half g_Kl[(size_t)NN * DM];
__device__ __half g_VT[(size_t)DM * NN];          // V^T fp16: g_VT[j][n] = V[n][j]

// ---------------- helpers ----------------
__device__ __forceinline__ uint32_t smem_u32(const void* p) {
    uint32_t a;
    asm("{ .reg .u64 t; cvta.to.shared.u64 t, %1; cvt.u32.u64 %0, t; }" : "=r"(a) : "l"(p));
    return a;
}

__device__ __forceinline__ void ldsm_x4(uint32_t* r, uint32_t addr) {
    asm volatile("ldmatrix.sync.aligned.m8n8.x4.shared.b16 {%0,%1,%2,%3}, [%4];"
                 : "=r"(r[0]), "=r"(r[1]), "=r"(r[2]), "=r"(r[3]) : "r"(addr));
}

__device__ __forceinline__ void mma16816(float* c, const uint32_t* a, const uint32_t* b) {
    asm volatile(
        "mma.sync.aligned.m16n8k16.row.col.f32.f16.f16.f32 "
        "{%0,%1,%2,%3}, {%4,%5,%6,%7}, {%8,%9}, {%0,%1,%2,%3};"
        : "+f"(c[0]), "+f"(c[1]), "+f"(c[2]), "+f"(c[3])
        : "r"(a[0]), "r"(a[1]), "r"(a[2]), "r"(a[3]), "r"(b[0]), "r"(b[1]));
}

__device__ __forceinline__ void cp16(uint32_t smem, const void* gmem) {
    asm volatile("cp.async.cg.shared.global [%0], [%1], 16;" :: "r"(smem), "l"(gmem));
}

// ---------------- kernel 1: R^T = rescale(dist)^T, fp16 split ----------------
__global__ void __launch_bounds__(1024) k_rescale(const float* __restrict__ dist) {
    __shared__ float t[32][33];
    const int m0 = blockIdx.y * 32, p0 = blockIdx.x * 32;
    const int tx = threadIdx.x, ty = threadIdx.y;
    float d = dist[(size_t)(m0 + ty) * NN + p0 + tx];
    t[ty][tx] = 3.718281828459045f / (1.0f + __expf(1.0f - d));
    __syncthreads();
    float r = t[tx][ty];  // = R[m0+tx][p0+ty]
    __half hi = __float2half(r);
    float lo = r - __half2float(hi);
    size_t o = (size_t)(p0 + ty) * NN + m0 + tx;
    g_RT_hi[o] = hi;
    g_RT_lo[o] = __float2half(lo);
}

// ---------------- kernel 2a: Q/K projections, tiled 64x64, 4x4 microtile ----------------
__global__ void __launch_bounds__(256) k_projqk(const float* __restrict__ Qin,
                                                const float* __restrict__ Kin,
                                                const float* __restrict__ WQ,
                                                const float* __restrict__ WK) {
    const float* __restrict__ X = blockIdx.z ? Kin : Qin;
    const float* __restrict__ W = blockIdx.z ? WK : WQ;
    __half* Oh = blockIdx.z ? g_Kh : g_Qh;
    __half* Ol = blockIdx.z ? g_Kl : g_Ql;

    __shared__ float Xs[32][68];
    __shared__ float Ws[32][68];
    const int j0g = blockIdx.x * 64, n0g = blockIdx.y * 64;
    const int tid = threadIdx.x;
    const int jt = (tid & 15) * 4;
    const int nt = (tid >> 4) * 4;
    const int lr = tid >> 2;
    const int lc = (tid & 3) * 8;

    float acc[4][4];
#pragma unroll
    for (int a = 0; a < 4; a++)
#pragma unroll
        for (int b = 0; b < 4; b++) acc[a][b] = 0.f;

    for (int k0 = 0; k0 < DM; k0 += 32) {
        __syncthreads();
        float4 a0 = *(const float4*)&X[(size_t)(n0g + lr) * DM + k0 + lc];
        float4 a1 = *(const float4*)&X[(size_t)(n0g + lr) * DM + k0 + lc + 4];
        Xs[lc + 0][lr] = a0.x; Xs[lc + 1][lr] = a0.y; Xs[lc + 2][lr] = a0.z; Xs[lc + 3][lr] = a0.w;
        Xs[lc + 4][lr] = a1.x; Xs[lc + 5][lr] = a1.y; Xs[lc + 6][lr] = a1.z; Xs[lc + 7][lr] = a1.w;
        float4 b0 = *(const float4*)&W[(size_t)(j0g + lr) * DM + k0 + lc];
        float4 b1 = *(const float4*)&W[(size_t)(j0g + lr) * DM + k0 + lc + 4];
        Ws[lc + 0][lr] = b0.x; Ws[lc + 1][lr] = b0.y; Ws[lc + 2][lr] = b0.z; Ws[lc + 3][lr] = b0.w;
        Ws[lc + 4][lr] = b1.x; Ws[lc + 5][lr] = b1.y; Ws[lc + 6][lr] = b1.z; Ws[lc + 7][lr] = b1.w;
        __syncthreads();
#pragma unroll
        for (int kk = 0; kk < 32; kk++) {
            float4 xv = *(const float4*)&Xs[kk][nt];
            float4 wv = *(const float4*)&Ws[kk][jt];
            const float xr[4] = {xv.x, xv.y, xv.z, xv.w};
            const float wr[4] = {wv.x, wv.y, wv.z, wv.w};
#pragma unroll
            for (int a = 0; a < 4; a++)
#pragma unroll
                for (int b = 0; b < 4; b++) acc[a][b] += xr[a] * wr[b];
        }
    }

#pragma unroll
    for (int a = 0; a < 4; a++) {
        const int n = n0g + nt + a;
        __half h[4], l[4];
#pragma unroll
        for (int b = 0; b < 4; b++) {
            h[b] = __float2half(acc[a][b]);
            l[b] = __float2half(acc[a][b] - __half2float(h[b]));
        }
        const size_t o = (size_t)n * DM + j0g + jt;
        *(__half2*)&Oh[o] = __halves2half2(h[0], h[1]);
        *(__half2*)&Oh[o + 2] = __halves2half2(h[2], h[3]);
        *(__half2*)&Ol[o] = __halves2half2(l[0], l[1]);
        *(__half2*)&Ol[o + 2] = __halves2half2(l[2], l[3]);
    }
}

// ---------------- kernel 2b: V projection (transposed fp16 out) ----------------
__global__ void __launch_bounds__(1024) k_projv(const float* __restrict__ X,
                                                const float* __restrict__ W) {
    __shared__ float Xs[32][33], Ws[32][33];
    const int n0 = blockIdx.y * 32, j0 = blockIdx.x * 32;
    const int tx = threadIdx.x, ty = threadIdx.y;
    float acc = 0.f;
    for (int k0 = 0; k0 < DM; k0 += 32) {
        Xs[ty][tx] = X[(size_t)(n0 + ty) * DM + k0 + tx];
        Ws[ty][tx] = W[(size_t)(j0 + ty) * DM + k0 + tx];
        __syncthreads();
#pragma unroll
        for (int kk = 0; kk < 32; kk++) acc += Xs[ty][kk] * Ws[tx][kk];
        __syncthreads();
    }
    __syncthreads();
    Xs[ty][tx] = acc;
    __syncthreads();
    float v = Xs[tx][ty];
    g_VT[(size_t)(j0 + ty) * NN + n0 + tx] = __float2half(v);
}

// ---------------- kernel 3: P = relu(Q K^T) via HMMA, split precision ----------------
// Epilogue staged through smem for coalesced 256B row-segment stores.
#define QK_ROWB 80
#define QK_ARR (128 * QK_ROWB)   // 10240
#define QK_STG_STRIDE 136        // halves per staged row (272B)

__global__ void __launch_bounds__(256, 2) k_qk_mma() {
    __shared__ char qsm[4 * QK_ARR];   // operands; reused as 128x136 half staging (34816B)
    const uint32_t sb = smem_u32(qsm);
    const int tid = threadIdx.x;
    const int wid = tid >> 5, lane = tid & 31;
    const int h = blockIdx.z;
    const int m0 = blockIdx.x * 128;   // key tile
    const int n0 = blockIdx.y * 128;   // query tile

    {
        const int r0 = tid >> 2, c = tid & 3;
#pragma unroll
        for (int j = 0; j < 2; j++) {
            const int r = r0 + j * 64;
            const uint32_t so = (uint32_t)(r * QK_ROWB + c * 16);
            const size_t qo = (size_t)(n0 + r) * DM + h * DH + c * 8;
            const size_t ko = (size_t)(m0 + r) * DM + h * DH + c * 8;
            cp16(sb + 0 * QK_ARR + so, g_Qh + qo);
            cp16(sb + 1 * QK_ARR + so, g_Ql + qo);
            cp16(sb + 2 * QK_ARR + so, g_Kh + ko);
            cp16(sb + 3 * QK_ARR + so, g_Kl + ko);
        }
    }
    asm volatile("cp.async.commit_group;" ::: "memory");
    asm volatile("cp.async.wait_group 0;" ::: "memory");
    __syncthreads();

    const int wm = wid & 1, wn = wid >> 1;
    float acc[4][4][4];
#pragma unroll
    for (int mi = 0; mi < 4; mi++)
#pragma unroll
        for (int ni = 0; ni < 4; ni++)
#pragma unroll
            for (int q = 0; q < 4; q++) acc[mi][ni][q] = 0.f;

    const int sel = lane >> 3, l7 = lane & 7;
    const int a_row = wm * 64 + (sel & 1) * 8 + l7;
    const int a_colb = (sel >> 1) * 16;
    const int b_row_base = wn * 32 + (sel >> 1) * 8 + l7;
    const int b_colb = (sel & 1) * 16;

#pragma unroll
    for (int ks = 0; ks < 2; ks++) {
        const int kb = ks * 32;
        uint32_t ahi[4][4], alo[4][4];
#pragma unroll
        for (int mi = 0; mi < 4; mi++) {
            const uint32_t ao = (uint32_t)((a_row + mi * 16) * QK_ROWB + kb + a_colb);
            ldsm_x4(ahi[mi], sb + 0 * QK_ARR + ao);
            ldsm_x4(alo[mi], sb + 1 * QK_ARR + ao);
        }
        uint32_t bhi[4][2], blo[4][2];
#pragma unroll
        for (int nb = 0; nb < 2; nb++) {
            const uint32_t bo = (uint32_t)((b_row_base + nb * 16) * QK_ROWB + kb + b_colb);
            uint32_t t[4];
            ldsm_x4(t, sb + 2 * QK_ARR + bo);
            bhi[2 * nb][0] = t[0]; bhi[2 * nb][1] = t[1];
            bhi[2 * nb + 1][0] = t[2]; bhi[2 * nb + 1][1] = t[3];
            ldsm_x4(t, sb + 3 * QK_ARR + bo);
            blo[2 * nb][0] = t[0]; blo[2 * nb][1] = t[1];
            blo[2 * nb + 1][0] = t[2]; blo[2 * nb + 1][1] = t[3];
        }
#pragma unroll
        for (int mi = 0; mi < 4; mi++)
#pragma unroll
            for (int ni = 0; ni < 4; ni++) mma16816(acc[mi][ni], ahi[mi], bhi[ni]);
#pragma unroll
        for (int mi = 0; mi < 4; mi++)
#pragma unroll
            for (int ni = 0; ni < 4; ni++) mma16816(acc[mi][ni], ahi[mi], blo[ni]);
#pragma unroll
        for (int mi = 0; mi < 4; mi++)
#pragma unroll
            for (int ni = 0; ni < 4; ni++) mma16816(acc[mi][ni], alo[mi], bhi[ni]);
    }

    // staged epilogue: two planes (hi, lo)
    __half* stg = (__half*)qsm;
    const int er = lane >> 2, ec = (lane & 3) * 2;
#pragma unroll
    for (int plane = 0; plane < 2; plane++) {
        __syncthreads();
#pragma unroll
        for (int mi = 0; mi < 4; mi++) {
#pragma unroll
            for (int ni = 0; ni < 4; ni++) {
                const int nl = wm * 64 + mi * 16 + er;       // n-local (row)
                const int ml = wn * 32 + ni * 8 + ec;        // m-local (col)
#pragma unroll
                for (int half = 0; half < 2; half++) {
                    float p0 = fmaxf(acc[mi][ni][2 * half + 0], 0.f);
                    float p1 = fmaxf(acc[mi][ni][2 * half + 1], 0.f);
                    __half v0, v1;
                    if (plane == 0) { v0 = __float2half(p0); v1 = __float2half(p1); }
                    else {
                        __half h0 = __float2half(p0), h1 = __float2half(p1);
                        v0 = __float2half(p0 - __half2float(h0));
                        v1 = __float2half(p1 - __half2float(h1));
                    }
                    *(__half2*)&stg[(nl + half * 8) * QK_STG_STRIDE + ml] = __halves2half2(v0, v1);
                }
            }
        }
        __syncthreads();
        __half* dst = plane == 0 ? g_P_hi : g_P_lo;
#pragma unroll
        for (int i = 0; i < 8; i++) {
            const int idx = i * 256 + tid;
            const int r = idx >> 4, c = idx & 15;      // 16 x 16B chunks per 128-half row
            uint4 v = *(uint4*)&stg[r * QK_STG_STRIDE + c * 8];
            *(uint4*)(dst + ((size_t)h * NN + n0 + r) * NN + m0 + c * 8) = v;
        }
    }
}

// ---------------- kernel 4: big GEMM (HMMA, split precision) ----------------
// CTA tile 256(M) x 128(N), K-chunk 64, 2-stage cp.async, 512 threads, 1 CTA/SM.
// Direct-store epilogue (round-14 form; staged variant measured slower here).
#define ROWB 144
#define A_ARR (256 * ROWB)               // 36864
#define B_ARR (128 * ROWB)               // 18432
#define STAGE_SZ (2 * A_ARR + 2 * B_ARR) // 110592
#define GEMM_SMEM (2 * STAGE_SZ)         // 221184
#define KITERS (NN / 64)                 // 64

__global__ void __launch_bounds__(512, 1) k_gemm() {
    extern __shared__ char smem[];
    const uint32_t sb = smem_u32(smem);
    const int tid = threadIdx.x;
    const int wid = tid >> 5, lane = tid & 31;
    const int h = blockIdx.y;

    // swizzle: groups of 8(m) x 16(n) CTAs -> 64MB working set, fits L2
    const int bid = blockIdx.x;          // 0..511
    const int g = bid >> 7;              // 0..3
    const int gx = g & 1, gy = g >> 1;
    const int ny = gy * 8 + (bid & 7);          // m-tile (256 rows)
    const int nx = gx * 16 + ((bid >> 3) & 15); // n-tile (128 cols)
    const int m0 = ny * 256, n0 = nx * 128;

    const __half* __restrict__ Ahi = g_P_hi + ((size_t)h * NN + m0) * NN;
    const __half* __restrict__ Alo = g_P_lo + ((size_t)h * NN + m0) * NN;
    const __half* __restrict__ Bhi = g_RT_hi + (size_t)n0 * NN;
    const __half* __restrict__ Blo = g_RT_lo + (size_t)n0 * NN;

    const int rl = tid >> 3, cl = tid & 7;   // loader: 64 rows x 8 chunks per pass

    auto issue_stage = [&](int it) {
        if (it < KITERS) {
            const uint32_t s0 = sb + (it & 1) * STAGE_SZ;
            const int kc = it * 64;
#pragma unroll
            for (int i = 0; i < 4; i++) {        // A: 256 rows
                const int r = rl + i * 64;
                const uint32_t so = (uint32_t)(r * ROWB + cl * 16);
                const size_t go = (size_t)r * NN + kc + cl * 8;
                cp16(s0 + 0 * A_ARR + so, Ahi + go);
                cp16(s0 + 1 * A_ARR + so, Alo + go);
            }
#pragma unroll
            for (int i = 0; i < 2; i++) {        // B: 128 rows
                const int r = rl + i * 64;
                const uint32_t so = (uint32_t)(r * ROWB + cl * 16);
                const size_t go = (size_t)r * NN + kc + cl * 8;
                cp16(s0 + 2 * A_ARR + 0 * B_ARR + so, Bhi + go);
                cp16(s0 + 2 * A_ARR + 1 * B_ARR + so, Blo + go);
            }
        }
        asm volatile("cp.async.commit_group;" ::: "memory");
    };

    // warp layout: 4 (M) x 4 (N); warp tile 64 (M) x 32 (N)
    const int wm = wid & 3, wn = wid >> 2;
    float acc[4][4][4];
#pragma unroll
    for (int mi = 0; mi < 4; mi++)
#pragma unroll
        for (int ni = 0; ni < 4; ni++)
#pragma unroll
            for (int q = 0; q < 4; q++) acc[mi][ni][q] = 0.f;

    const int sel = lane >> 3, l7 = lane & 7;
    const int a_row = wm * 64 + (sel & 1) * 8 + l7;
    const int a_colb = (sel >> 1) * 16;
    const int b_row_base = wn * 32 + (sel >> 1) * 8 + l7;
    const int b_colb = (sel & 1) * 16;

    issue_stage(0);

    for (int it = 0; it < KITERS; it++) {
        asm volatile("cp.async.wait_group 0;" ::: "memory");
        __syncthreads();            // all warps past previous compute; this stage visible
        issue_stage(it + 1);        // fill other buffer while computing this one

        const uint32_t s0 = sb + (it & 1) * STAGE_SZ;
        const uint32_t pAhi = s0, pAlo = s0 + A_ARR;
        const uint32_t pBhi = s0 + 2 * A_ARR, pBlo = pBhi + B_ARR;

#pragma unroll
        for (int ks = 0; ks < 4; ks++) {   // four k16 steps within the 64-chunk
            const int kb = ks * 32;
            uint32_t ahi[4][4], alo[4][4];
#pragma unroll
            for (int mi = 0; mi < 4; mi++) {
                const uint32_t ao = (uint32_t)((a_row + mi * 16) * ROWB + kb + a_colb);
                ldsm_x4(ahi[mi], pAhi + ao);
                ldsm_x4(alo[mi], pAlo + ao);
            }
            uint32_t bhi[4][2], blo[4][2];
#pragma unroll
            for (int nb = 0; nb < 2; nb++) {
                const uint32_t bo = (uint32_t)((b_row_base + nb * 16) * ROWB + kb + b_colb);
                uint32_t t[4];
                ldsm_x4(t, pBhi + bo);
                bhi[2 * nb][0] = t[0]; bhi[2 * nb][1] = t[1];
                bhi[2 * nb + 1][0] = t[2]; bhi[2 * nb + 1][1] = t[3];
                ldsm_x4(t, pBlo + bo);
                blo[2 * nb][0] = t[0]; blo[2 * nb][1] = t[1];
                blo[2 * nb + 1][0] = t[2]; blo[2 * nb + 1][1] = t[3];
            }
#pragma unroll
            for (int mi = 0; mi < 4; mi++)
#pragma unroll
                for (int ni = 0; ni < 4; ni++) mma16816(acc[mi][ni], ahi[mi], bhi[ni]);
#pragma unroll
            for (int mi = 0; mi < 4; mi++)
#pragma unroll
                for (int ni = 0; ni < 4; ni++) mma16816(acc[mi][ni], ahi[mi], blo[ni]);
#pragma unroll
            for (int mi = 0; mi < 4; mi++)
#pragma unroll
                for (int ni = 0; ni < 4; ni++) mma16816(acc[mi][ni], alo[mi], bhi[ni]);
        }
    }

    // epilogue (direct stores)
    const float inv_s = 0.17677669529663687f;  // 1/sqrt(32)
    const int er = lane >> 2, ec = (lane & 3) * 2;
#pragma unroll
    for (int mi = 0; mi < 4; mi++) {
#pragma unroll
        for (int ni = 0; ni < 4; ni++) {
            const int col = n0 + wn * 32 + ni * 8 + ec;
            const int row = m0 + wm * 64 + mi * 16 + er;
            float2 v0 = make_float2(acc[mi][ni][0] * inv_s, acc[mi][ni][1] * inv_s);
            float2 v1 = make_float2(acc[mi][ni][2] * inv_s, acc[mi][ni][3] * inv_s);
            *(float2*)(g_S + ((size_t)h * NN + row) * NN + col) = v0;
            *(float2*)(g_S + ((size_t)h * NN + row + 8) * NN + col) = v1;
        }
    }
}

// ---------------- kernel 5: softmax, warp-granular exp skip; fp16 attn out ----------------
__global__ void __launch_bounds__(256) k_softmax() {
    const size_t row = blockIdx.x;
    const float* p = g_S + row * (size_t)NN;
    __half* pa = g_P_hi + row * (size_t)NN;
    const int tid = threadIdx.x;
    float x[16];
    float mx = -1e30f;
#pragma unroll
    for (int i = 0; i < 16; i++) { x[i] = p[tid + (i << 8)]; mx = fmaxf(mx, x[i]); }
    __shared__ float red[8];
#pragma unroll
    for (int o = 16; o; o >>= 1) mx = fmaxf(mx, __shfl_xor_sync(0xffffffffu, mx, o));
    if ((tid & 31) == 0) red[tid >> 5] = mx;
    __syncthreads();
    mx = red[0];
#pragma unroll
    for (int i = 1; i < 8; i++) mx = fmaxf(mx, red[i]);
    const float thr = mx - 20.0f;
    float s = 0.f;
#pragma unroll
    for (int i = 0; i < 16; i++) {
        if (__any_sync(0xffffffffu, x[i] >= thr)) {
            x[i] = (x[i] >= thr) ? __expf(x[i] - mx) : 0.f;
            s += x[i];
        } else {
            x[i] = 0.f;
        }
    }
#pragma unroll
    for (int o = 16; o; o >>= 1) s += __shfl_xor_sync(0xffffffffu, s, o);
    __syncthreads();
    if ((tid & 31) == 0) red[tid >> 5] = s;
    __syncthreads();
    s = ((red[0] + red[1]) + (red[2] + red[3])) + ((red[4] + red[5]) + (red[6] + red[7]));
    const float inv = 1.0f / s;
#pragma unroll
    for (int i = 0; i < 16; i++) pa[tid + (i << 8)] = __float2half(x[i] * inv);
}

// ---------------- kernel 6: out = attn @ V via HMMA ----------------
#define AV_ROWB 272
#define AV_A (64 * AV_ROWB)
#define AV_B (32 * AV_ROWB)
#define AV_STAGE (AV_A + AV_B)
#define AV_SMEM (2 * AV_STAGE)
#define AV_KITERS (NN / 128)

__global__ void __launch_bounds__(256) k_av(float* __restrict__ out) {
    extern __shared__ char avsm[];
    const uint32_t sb = smem_u32(avsm);
    const int tid = threadIdx.x;
    const int wid = tid >> 5, lane = tid & 31;
    const int h = blockIdx.y, n0 = blockIdx.x * 64;

    const __half* __restrict__ A = g_P_hi + ((size_t)h * NN + n0) * NN;   // attn rows
    const __half* __restrict__ B = g_VT + (size_t)(h * DH) * NN;          // V^T rows (d)

    auto issue_stage = [&](int it) {
        if (it < AV_KITERS) {
            const uint32_t s0 = sb + (it & 1) * AV_STAGE;
            const int kc = it * 128;
#pragma unroll
            for (int i = 0; i < 4; i++) {
                const int idx = i * 256 + tid;
                const int r = idx >> 4, c = idx & 15;
                cp16(s0 + (uint32_t)(r * AV_ROWB + c * 16), A + (size_t)r * NN + kc + c * 8);
            }
#pragma unroll
            for (int i = 0; i < 2; i++) {
                const int idx = i * 256 + tid;
                const int r = idx >> 4, c = idx & 15;
                cp16(s0 + AV_A + (uint32_t)(r * AV_ROWB + c * 16), B + (size_t)r * NN + kc + c * 8);
            }
        }
        asm volatile("cp.async.commit_group;" ::: "memory");
    };

    const int wm = wid & 3, wn = wid >> 2;
    float acc[2][4];
#pragma unroll
    for (int ni = 0; ni < 2; ni++)
#pragma unroll
        for (int q = 0; q < 4; q++) acc[ni][q] = 0.f;

    const int sel = lane >> 3, l7 = lane & 7;
    const int a_row = wm * 16 + (sel & 1) * 8 + l7;
    const int a_colb = (sel >> 1) * 16;
    const int b_row = wn * 16 + (sel >> 1) * 8 + l7;
    const int b_colb = (sel & 1) * 16;

    issue_stage(0);

    for (int it = 0; it < AV_KITERS; it++) {
        asm volatile("cp.async.wait_group 0;" ::: "memory");
        __syncthreads();
        issue_stage(it + 1);

        const uint32_t s0 = sb + (it & 1) * AV_STAGE;
#pragma unroll
        for (int ks = 0; ks < 8; ks++) {
            const int kb = ks * 32;
            uint32_t a[4], b[4];
            ldsm_x4(a, s0 + (uint32_t)(a_row * AV_ROWB + kb + a_colb));
            ldsm_x4(b, s0 + AV_A + (uint32_t)(b_row * AV_ROWB + kb + b_colb));
            mma16816(acc[0], a, b + 0);
            mma16816(acc[1], a, b + 2);
        }
    }

    const int er = lane >> 2, ec = (lane & 3) * 2;
    const int n = n0 + wm * 16 + er;
#pragma unroll
    for (int ni = 0; ni < 2; ni++) {
        const int d = wn * 16 + ni * 8 + ec;
        *(float2*)(out + (size_t)n * DM + h * DH + d) = make_float2(acc[ni][0], acc[ni][1]);
        *(float2*)(out + (size_t)(n + 8) * DM + h * DH + d) = make_float2(acc[ni][2], acc[ni][3]);
    }
}

// ---------------- launch ----------------
extern "C" void kernel_launch(void* const* d_in, const int* in_sizes, int n_in,
                              void* d_out, int out_size) {
    (void)in_sizes; (void)n_in; (void)out_size;
    const float* Qin  = (const float*)d_in[0];
    const float* Kin  = (const float*)d_in[1];
    const float* Vin  = (const float*)d_in[2];
    // d_in[3] = adj_matrix: dead code in the reference
    const float* dist = (const float*)d_in[4];
    const float* WQ   = (const float*)d_in[5];
    const float* WK   = (const float*)d_in[6];
    const float* WV   = (const float*)d_in[7];
    float* out = (float*)d_out;

    k_rescale<<<dim3(128, 128), dim3(32, 32)>>>(dist);
    k_projqk<<<dim3(4, 64, 2), 256>>>(Qin, Kin, WQ, WK);
    k_projv<<<dim3(8, 128), dim3(32, 32)>>>(Vin, WV);
    k_qk_mma<<<dim3(32, 32, 8), 256>>>();

    cudaFuncSetAttribute(k_gemm, cudaFuncAttributeMaxDynamicSharedMemorySize, GEMM_SMEM);
    k_gemm<<<dim3(512, 8), 512, GEMM_SMEM>>>();

    k_softmax<<<dim3(NH * NN), 256>>>();

    cudaFuncSetAttribute(k_av, cudaFuncAttributeMaxDynamicSharedMemorySize, AV_SMEM);
    k_av<<<dim3(64, 8), 256, AV_SMEM>>>(out);
}